// round 15
// baseline (speedup 1.0000x reference)
#include <cuda_runtime.h>
#include <cstdint>
#include <stdint.h>

#define B_SZ   256
#define T_SZ   2048
#define N_SZ   128
#define NPAIRS (B_SZ * T_SZ)   // 524288

#define WROW   132
#define WROW4  33
#define BSROW  129

// Scratch (device globals — no allocation allowed)
__device__ __align__(16) float  g_h[NPAIRS * 2];  // hidden, [t][b] float2 layout
__device__ __align__(16) float2 g_c[NPAIRS];      // input proj, [t][b] float2
__device__ __align__(16) float  g_q0[N_SZ];       // Q[:,0]
__device__ __align__(16) float  g_q1[N_SZ];       // Q[:,1]
__device__ int g_prog[8];                         // per-RNN-block chunk progress
__device__ int g_qdone;                           // solve finished flag

__device__ __forceinline__ float fast_rcp(float x) {
    float r;
    asm("rcp.approx.f32 %0, %1;" : "=f"(r) : "f"(x));
    return r;
}

// ---------------------------------------------------------------------------
// Kernel 0: input projection  c[t][b] = 0.1 * wIn @ u[b,t,:]
// Also resets the phase1 progress flags (stream order makes this safe).
// ---------------------------------------------------------------------------
__global__ void __launch_bounds__(256) proj_kernel(const float* __restrict__ u,
                                                   const float* __restrict__ wIn) {
    if (blockIdx.x == 0 && threadIdx.x < 9) {
        if (threadIdx.x < 8) g_prog[threadIdx.x] = 0;
        else                 g_qdone = 0;
    }

    const float I00 = 0.1f * __ldg(wIn + 0), I01 = 0.1f * __ldg(wIn + 1),
                I02 = 0.1f * __ldg(wIn + 2);
    const float I10 = 0.1f * __ldg(wIn + 3), I11 = 0.1f * __ldg(wIn + 4),
                I12 = 0.1f * __ldg(wIn + 5);

    int p4 = (int)blockIdx.x * 256 + (int)threadIdx.x;   // 0..131071
    int b  = p4 >> 9;
    int t0 = (p4 & 511) << 2;

    const float4* up = (const float4*)(u + (size_t)b * (T_SZ * 3) + (size_t)t0 * 3);
    float4 v0 = __ldg(up + 0);
    float4 v1 = __ldg(up + 1);
    float4 v2 = __ldg(up + 2);

    float2* outp = g_c + (size_t)t0 * B_SZ + b;
    outp[0]         = make_float2(fmaf(I00, v0.x, fmaf(I01, v0.y, I02 * v0.z)),
                                  fmaf(I10, v0.x, fmaf(I11, v0.y, I12 * v0.z)));
    outp[B_SZ]      = make_float2(fmaf(I00, v0.w, fmaf(I01, v1.x, I02 * v1.y)),
                                  fmaf(I10, v0.w, fmaf(I11, v1.x, I12 * v1.y)));
    outp[2 * B_SZ]  = make_float2(fmaf(I00, v1.z, fmaf(I01, v1.w, I02 * v2.x)),
                                  fmaf(I10, v1.z, fmaf(I11, v1.w, I12 * v2.x)));
    outp[3 * B_SZ]  = make_float2(fmaf(I00, v2.y, fmaf(I01, v2.z, I02 * v2.w)),
                                  fmaf(I10, v2.y, fmaf(I11, v2.z, I12 * v2.w)));
}

// ---------------------------------------------------------------------------
// Phase 1 (148 blocks x 256 threads, 1 block/SM, ALL co-resident):
//   block 0:      Cayley solve -> publishes g_qdone
//   blocks 1..8:  leaky RNN (1 warp, 32 seqs) -> publishes g_prog per chunk
//   blocks 9..147: expand consumers — 1024 warps, 4 per sequence, spin on
//                  producer flags and stream out[b][t][:] as h arrives
// ---------------------------------------------------------------------------
__global__ void __launch_bounds__(256) phase1_kernel(
        const float* __restrict__ matB,
        const float* __restrict__ wRec,
        float* __restrict__ out) {
    extern __shared__ float smem[];
    const int tid  = threadIdx.x;
    const int lane = tid & 31;
    const int wid  = tid >> 5;

    if (blockIdx.x == 0) {
        // ================= Cayley solve =================
        float*  Wf     = smem;                           // [128][132]
        float4* W4     = (float4*)smem;                  // stride 33
        float*  Bs     = smem + N_SZ * WROW;             // [128][129]
        float*  prowf  = Bs + N_SZ * BSROW;              // [4][132]
        float4* prow4  = (float4*)prowf;                 // [4][33]
        float*  rinv_s = prowf + 4 * WROW;               // [4]
        __shared__ float z0s[N_SZ], z1s[N_SZ];
        const int row  = tid & 127;
        const int half = tid >> 7;

        for (int idx = tid; idx < N_SZ * 32; idx += 256) {
            int r = idx >> 5, c4 = idx & 31;
            float4 v = ((const float4*)matB)[r * 32 + c4];
            float* dst = Bs + r * BSROW + c4 * 4;
            dst[0] = v.x; dst[1] = v.y; dst[2] = v.z; dst[3] = v.w;
        }
        __syncthreads();

        if (half == 0) {
            float* wr = Wf + row * WROW;
            #pragma unroll 4
            for (int j = 0; j < N_SZ; j++) {
                float a = Bs[row * BSROW + j] - Bs[j * BSROW + row];
                wr[j] = (row == j ? 1.0f : 0.0f) + a;
            }
            wr[128] = (row == 0) ? 1.0f : 0.0f;
            wr[129] = (row == 1) ? 1.0f : 0.0f;
            wr[130] = 0.0f; wr[131] = 0.0f;
        }
        __syncthreads();

        for (int p = 0; p < 32; p++) {
            if (wid == 0) {
                const unsigned FULL = 0xffffffffu;
                float4 pr[4];
                float4 pr32[4];
                float  rv[4];
                #pragma unroll
                for (int m = 0; m < 4; m++) {
                    const int k = 4 * p + m;
                    float4 v   = W4[k * WROW4 + lane];
                    float4 v32 = make_float4(0.f, 0.f, 0.f, 0.f);
                    if (lane == 0) v32 = W4[k * WROW4 + 32];
                    #pragma unroll
                    for (int j = 0; j < 3; j++) {
                        if (j < m) {
                            float elem = (j == 0) ? v.x : ((j == 1) ? v.y : v.z);
                            float fj = __shfl_sync(FULL, elem * rv[j], p);
                            v.x = fmaf(-fj, pr[j].x, v.x);
                            v.y = fmaf(-fj, pr[j].y, v.y);
                            v.z = fmaf(-fj, pr[j].z, v.z);
                            v.w = fmaf(-fj, pr[j].w, v.w);
                            if (lane == 0) {
                                v32.x = fmaf(-fj, pr32[j].x, v32.x);
                                v32.y = fmaf(-fj, pr32[j].y, v32.y);
                                v32.z = fmaf(-fj, pr32[j].z, v32.z);
                                v32.w = fmaf(-fj, pr32[j].w, v32.w);
                            }
                        }
                    }
                    float dg = (m == 0) ? v.x : ((m == 1) ? v.y : ((m == 2) ? v.z : v.w));
                    float rm = __shfl_sync(FULL, fast_rcp(dg), p);
                    rv[m] = rm;
                    pr[m] = v;
                    prow4[m * WROW4 + lane] = v;
                    if (lane == 0) {
                        pr32[m] = v32;
                        prow4[m * WROW4 + 32] = v32;
                        rinv_s[m] = rm;
                    }
                }
            }
            __syncthreads();

            if (row > 4 * p + 3) {
                float4 cp  = W4[row * WROW4 + p];
                float4 pp0 = prow4[0 * WROW4 + p];
                float4 pp1 = prow4[1 * WROW4 + p];
                float4 pp2 = prow4[2 * WROW4 + p];
                float r0 = rinv_s[0], r1 = rinv_s[1], r2 = rinv_s[2], r3 = rinv_s[3];

                float f0 = cp.x * r0;
                cp.y = fmaf(-f0, pp0.y, cp.y);
                float f1 = cp.y * r1;
                cp.z = fmaf(-f1, pp1.z, fmaf(-f0, pp0.z, cp.z));
                float f2 = cp.z * r2;
                cp.w = fmaf(-f2, pp2.w, fmaf(-f1, pp1.w, fmaf(-f0, pp0.w, cp.w)));
                float f3 = cp.w * r3;

                const float4* q0r = prow4 + 0 * WROW4;
                const float4* q1r = prow4 + 1 * WROW4;
                const float4* q2r = prow4 + 2 * WROW4;
                const float4* q3r = prow4 + 3 * WROW4;
                float4* wr = W4 + row * WROW4;
                #pragma unroll 2
                for (int g = p + 1 + half; g < WROW4; g += 2) {
                    float4 a  = wr[g];
                    float4 q0 = q0r[g], q1 = q1r[g], q2 = q2r[g], q3 = q3r[g];
                    a.x = fmaf(-f0, q0.x, fmaf(-f1, q1.x, fmaf(-f2, q2.x, fmaf(-f3, q3.x, a.x))));
                    a.y = fmaf(-f0, q0.y, fmaf(-f1, q1.y, fmaf(-f2, q2.y, fmaf(-f3, q3.y, a.y))));
                    a.z = fmaf(-f0, q0.z, fmaf(-f1, q1.z, fmaf(-f2, q2.z, fmaf(-f3, q3.z, a.z))));
                    a.w = fmaf(-f0, q0.w, fmaf(-f1, q1.w, fmaf(-f2, q2.w, fmaf(-f3, q3.w, a.w))));
                    wr[g] = a;
                }
            } else {
                int cidx   = row * 2 + half;
                int stride = 8 * (p + 1);
                for (int idx = cidx; idx < 4 * WROW4; idx += stride)
                    W4[(4 * p + idx / WROW4) * WROW4 + (idx % WROW4)] = prow4[idx];
            }
            __syncthreads();
        }

        for (int k = N_SZ - 1; k >= 0; k--) {
            if (half == 0) {
                float rinv = fast_rcp(Wf[k * WROW + k]);
                float zk0 = Wf[k * WROW + 128] * rinv;
                float zk1 = Wf[k * WROW + 129] * rinv;
                if (row < k) {
                    float a = Wf[row * WROW + k];
                    Wf[row * WROW + 128] = fmaf(-a, zk0, Wf[row * WROW + 128]);
                    Wf[row * WROW + 129] = fmaf(-a, zk1, Wf[row * WROW + 129]);
                } else if (row == k) {
                    z0s[k] = zk0;
                    z1s[k] = zk1;
                }
            }
            __syncthreads();
        }

        if (half == 0) {
            float q0 = z0s[row], q1 = z1s[row];
            #pragma unroll 4
            for (int k = 0; k < N_SZ; k++) {
                float a = Bs[row * BSROW + k] - Bs[k * BSROW + row];
                q0 = fmaf(-a, z0s[k], q0);
                q1 = fmaf(-a, z1s[k], q1);
            }
            g_q0[row] = q0;
            g_q1[row] = q1;
        }
        __syncthreads();
        __threadfence();
        if (tid == 0) *(volatile int*)&g_qdone = 1;
    } else if (blockIdx.x <= 8) {
        // ====== Leaky RNN producer: 1 warp, 32 seqs, publish per chunk ======
        if (tid >= 32) return;
        const int j   = (int)blockIdx.x - 1;     // RNN block id
        const int seq = j * 32 + tid;

        const float W00 = 0.1f * wRec[0], W01 = 0.1f * wRec[1];
        const float W10 = 0.1f * wRec[2], W11 = 0.1f * wRec[3];

        const float2* gc = g_c;
        float2* hp = (float2*)g_h;
        float y0 = 0.0f, y1 = 0.0f;

        #define RNN_STEP2(CC, TT)                                               \
            {                                                                   \
                float a0 = fmaf(0.9f, y0, CC.x);                                \
                float a1 = fmaf(0.9f, y1, CC.y);                                \
                float r0 = fmaxf(y0, 0.0f);                                     \
                float r1 = fmaxf(y1, 0.0f);                                     \
                float t0 = fmaf(W00, r0, a0);                                   \
                float t1 = fmaf(W10, r0, a1);                                   \
                y0 = fmaf(W01, r1, t0);                                         \
                y1 = fmaf(W11, r1, t1);                                         \
                hp[(TT) * B_SZ + seq] = make_float2(y0, y1);                    \
            }

        #define LOADG(P, G)                                                     \
            {                                                                   \
                int gg_ = (G) < 255 ? (G) : 255;                                \
                const float2* cp_ = gc + (size_t)gg_ * 8 * B_SZ + seq;          \
                P##0 = __ldg(cp_ + 0 * B_SZ); P##1 = __ldg(cp_ + 1 * B_SZ);     \
                P##2 = __ldg(cp_ + 2 * B_SZ); P##3 = __ldg(cp_ + 3 * B_SZ);     \
                P##4 = __ldg(cp_ + 4 * B_SZ); P##5 = __ldg(cp_ + 5 * B_SZ);     \
                P##6 = __ldg(cp_ + 6 * B_SZ); P##7 = __ldg(cp_ + 7 * B_SZ);     \
            }

        #define RNN_G8(P, TB)                                                   \
            {                                                                   \
                RNN_STEP2(P##0, (TB) + 0); RNN_STEP2(P##1, (TB) + 1);           \
                RNN_STEP2(P##2, (TB) + 2); RNN_STEP2(P##3, (TB) + 3);           \
                RNN_STEP2(P##4, (TB) + 4); RNN_STEP2(P##5, (TB) + 5);           \
                RNN_STEP2(P##6, (TB) + 6); RNN_STEP2(P##7, (TB) + 7);           \
            }

        #define PUBLISH(CHV)                                                    \
            {                                                                   \
                __threadfence();                                                \
                if (tid == 0) *(volatile int*)&g_prog[j] = (CHV);               \
            }

        float2 A0, A1, A2, A3, A4, A5, A6, A7;
        float2 B0, B1, B2, B3, B4, B5, B6, B7;
        float2 C0, C1, C2, C3, C4, C5, C6, C7;
        float2 D0, D1, D2, D3, D4, D5, D6, D7;

        LOADG(A, 0); LOADG(B, 1); LOADG(C, 2);

        // 63 iterations of 4 groups (= 1 chunk of 32 steps each)
        #pragma unroll 1
        for (int g = 0; g < 252; g += 4) {
            LOADG(D, g + 3);
            RNN_G8(A, (g + 0) * 8);
            LOADG(A, g + 4);
            RNN_G8(B, (g + 1) * 8);
            LOADG(B, g + 5);
            RNN_G8(C, (g + 2) * 8);
            LOADG(C, g + 6);
            RNN_G8(D, (g + 3) * 8);
            PUBLISH((g >> 2) + 1);
        }
        // tail: groups 252..255 = chunk 63
        LOADG(D, 255);
        RNN_G8(A, 252 * 8);
        RNN_G8(B, 253 * 8);
        RNN_G8(C, 254 * 8);
        RNN_G8(D, 255 * 8);
        PUBLISH(64);

        #undef PUBLISH
        #undef RNN_G8
        #undef LOADG
        #undef RNN_STEP2
    } else {
        // ====== Expand consumers: 1024 warps, 4 per sequence ======
        const int gw = ((int)blockIdx.x - 9) * 8 + wid;
        if (gw >= 1024) return;
        const int b    = gw >> 2;        // sequence
        const int part = gw & 3;         // quarter of the timeline
        const int pj   = b >> 5;         // producer RNN block

        // wait for q
        if (lane == 0) {
            while (*(volatile int*)&g_qdone == 0) {}
        }
        __syncwarp();
        __threadfence();

        const float4 q0 = ((const float4*)g_q0)[lane];
        const float4 q1 = ((const float4*)g_q1)[lane];
        const float2* hp = (const float2*)g_h;
        float4* o = (float4*)out;

        for (int chunk = part * 16; chunk < part * 16 + 16; chunk++) {
            if (lane == 0) {
                while (*(volatile int*)&g_prog[pj] < chunk + 1) {}
            }
            __syncwarp();
            __threadfence();

            const int tb = chunk * 32;
            #pragma unroll 2
            for (int t4 = 0; t4 < 8; t4++) {
                int t = tb + t4 * 4;
                float2 h0 = hp[(t + 0) * B_SZ + b];
                float2 h1 = hp[(t + 1) * B_SZ + b];
                float2 h2 = hp[(t + 2) * B_SZ + b];
                float2 h3 = hp[(t + 3) * B_SZ + b];

                size_t base = ((size_t)b * T_SZ + t) * 32 + lane;
                float4 v;
                v.x = fmaf(h0.x, q0.x, h0.y * q1.x);
                v.y = fmaf(h0.x, q0.y, h0.y * q1.y);
                v.z = fmaf(h0.x, q0.z, h0.y * q1.z);
                v.w = fmaf(h0.x, q0.w, h0.y * q1.w);
                __stcs(&o[base], v);
                v.x = fmaf(h1.x, q0.x, h1.y * q1.x);
                v.y = fmaf(h1.x, q0.y, h1.y * q1.y);
                v.z = fmaf(h1.x, q0.z, h1.y * q1.z);
                v.w = fmaf(h1.x, q0.w, h1.y * q1.w);
                __stcs(&o[base + 32], v);
                v.x = fmaf(h2.x, q0.x, h2.y * q1.x);
                v.y = fmaf(h2.x, q0.y, h2.y * q1.y);
                v.z = fmaf(h2.x, q0.z, h2.y * q1.z);
                v.w = fmaf(h2.x, q0.w, h2.y * q1.w);
                __stcs(&o[base + 64], v);
                v.x = fmaf(h3.x, q0.x, h3.y * q1.x);
                v.y = fmaf(h3.x, q0.y, h3.y * q1.y);
                v.z = fmaf(h3.x, q0.z, h3.y * q1.z);
                v.w = fmaf(h3.x, q0.w, h3.y * q1.w);
                __stcs(&o[base + 96], v);
            }
        }
    }
}

// ---------------------------------------------------------------------------
extern "C" void kernel_launch(void* const* d_in, const int* in_sizes, int n_in,
                              void* d_out, int out_size) {
    // u = 1572864, matB = 16384, wIn = 6, wRec = 4
    const float *u = nullptr, *matB = nullptr, *wIn = nullptr, *wRec = nullptr;
    for (int i = 0; i < n_in; i++) {
        switch (in_sizes[i]) {
            case 1572864: u    = (const float*)d_in[i]; break;
            case 16384:   matB = (const float*)d_in[i]; break;
            case 6:       wIn  = (const float*)d_in[i]; break;
            case 4:       wRec = (const float*)d_in[i]; break;
        }
    }

    const int smem = (N_SZ * WROW + N_SZ * BSROW + 4 * WROW + 4)
                     * (int)sizeof(float);   // ~135.8 KB -> 1 block/SM
    cudaFuncSetAttribute(phase1_kernel,
                         cudaFuncAttributeMaxDynamicSharedMemorySize, smem);

    // 0) input projection + flag reset
    proj_kernel<<<512, 256>>>(u, wIn);

    // 1) fused solve + RNN + overlapped expand (148 co-resident blocks)
    phase1_kernel<<<148, 256, smem>>>(matB, wRec, (float*)d_out);
}

// round 16
// speedup vs baseline: 1.2640x; 1.2640x over previous
#include <cuda_runtime.h>
#include <cstdint>
#include <stdint.h>

#define B_SZ   256
#define T_SZ   2048
#define N_SZ   128
#define NPAIRS (B_SZ * T_SZ)   // 524288

#define WROW   132
#define WROW4  33
#define BSROW  129

// Scratch (device globals — no allocation allowed)
__device__ __align__(16) float  g_h[NPAIRS * 2];  // hidden, [t][b] float2 layout
__device__ __align__(16) float2 g_c[NPAIRS];      // input proj, [t][b] float2
__device__ __align__(16) float  g_q0[N_SZ];       // Q[:,0]
__device__ __align__(16) float  g_q1[N_SZ];       // Q[:,1]
__device__ int g_prog[8];                         // per-RNN-block 128-step units done
__device__ int g_qdone;                           // solve finished flag

__device__ __forceinline__ float fast_rcp(float x) {
    float r;
    asm("rcp.approx.f32 %0, %1;" : "=f"(r) : "f"(x));
    return r;
}

// ---------------------------------------------------------------------------
// Kernel 0: input projection  c[t][b] = 0.1 * wIn @ u[b,t,:]
// Also resets the phase1 progress flags (stream order makes this safe).
// ---------------------------------------------------------------------------
__global__ void __launch_bounds__(256) proj_kernel(const float* __restrict__ u,
                                                   const float* __restrict__ wIn) {
    if (blockIdx.x == 0 && threadIdx.x < 9) {
        if (threadIdx.x < 8) g_prog[threadIdx.x] = 0;
        else                 g_qdone = 0;
    }

    const float I00 = 0.1f * __ldg(wIn + 0), I01 = 0.1f * __ldg(wIn + 1),
                I02 = 0.1f * __ldg(wIn + 2);
    const float I10 = 0.1f * __ldg(wIn + 3), I11 = 0.1f * __ldg(wIn + 4),
                I12 = 0.1f * __ldg(wIn + 5);

    int p4 = (int)blockIdx.x * 256 + (int)threadIdx.x;   // 0..131071
    int b  = p4 >> 9;
    int t0 = (p4 & 511) << 2;

    const float4* up = (const float4*)(u + (size_t)b * (T_SZ * 3) + (size_t)t0 * 3);
    float4 v0 = __ldg(up + 0);
    float4 v1 = __ldg(up + 1);
    float4 v2 = __ldg(up + 2);

    float2* outp = g_c + (size_t)t0 * B_SZ + b;
    outp[0]         = make_float2(fmaf(I00, v0.x, fmaf(I01, v0.y, I02 * v0.z)),
                                  fmaf(I10, v0.x, fmaf(I11, v0.y, I12 * v0.z)));
    outp[B_SZ]      = make_float2(fmaf(I00, v0.w, fmaf(I01, v1.x, I02 * v1.y)),
                                  fmaf(I10, v0.w, fmaf(I11, v1.x, I12 * v1.y)));
    outp[2 * B_SZ]  = make_float2(fmaf(I00, v1.z, fmaf(I01, v1.w, I02 * v2.x)),
                                  fmaf(I10, v1.z, fmaf(I11, v1.w, I12 * v2.x)));
    outp[3 * B_SZ]  = make_float2(fmaf(I00, v2.y, fmaf(I01, v2.z, I02 * v2.w)),
                                  fmaf(I10, v2.y, fmaf(I11, v2.z, I12 * v2.w)));
}

// ---------------------------------------------------------------------------
// Phase 1 (148 blocks x 256 threads, 1 block/SM, ALL co-resident):
//   block 0:      Cayley solve -> publishes g_qdone
//   blocks 1..8:  leaky RNN (1 warp, 32 seqs) -> publishes g_prog every
//                 4 chunks (128 steps)  [16 fences total, not 63]
//   blocks 9..147: expand consumers — 1024 warps, 4 per sequence, poll with
//                 __nanosleep backoff and stream out[b][t][:] as h arrives
// ---------------------------------------------------------------------------
__global__ void __launch_bounds__(256) phase1_kernel(
        const float* __restrict__ matB,
        const float* __restrict__ wRec,
        float* __restrict__ out) {
    extern __shared__ float smem[];
    const int tid  = threadIdx.x;
    const int lane = tid & 31;
    const int wid  = tid >> 5;

    if (blockIdx.x == 0) {
        // ================= Cayley solve =================
        float*  Wf     = smem;                           // [128][132]
        float4* W4     = (float4*)smem;                  // stride 33
        float*  Bs     = smem + N_SZ * WROW;             // [128][129]
        float*  prowf  = Bs + N_SZ * BSROW;              // [4][132]
        float4* prow4  = (float4*)prowf;                 // [4][33]
        float*  rinv_s = prowf + 4 * WROW;               // [4]
        __shared__ float z0s[N_SZ], z1s[N_SZ];
        const int row  = tid & 127;
        const int half = tid >> 7;

        for (int idx = tid; idx < N_SZ * 32; idx += 256) {
            int r = idx >> 5, c4 = idx & 31;
            float4 v = ((const float4*)matB)[r * 32 + c4];
            float* dst = Bs + r * BSROW + c4 * 4;
            dst[0] = v.x; dst[1] = v.y; dst[2] = v.z; dst[3] = v.w;
        }
        __syncthreads();

        if (half == 0) {
            float* wr = Wf + row * WROW;
            #pragma unroll 4
            for (int j = 0; j < N_SZ; j++) {
                float a = Bs[row * BSROW + j] - Bs[j * BSROW + row];
                wr[j] = (row == j ? 1.0f : 0.0f) + a;
            }
            wr[128] = (row == 0) ? 1.0f : 0.0f;
            wr[129] = (row == 1) ? 1.0f : 0.0f;
            wr[130] = 0.0f; wr[131] = 0.0f;
        }
        __syncthreads();

        for (int p = 0; p < 32; p++) {
            if (wid == 0) {
                const unsigned FULL = 0xffffffffu;
                float4 pr[4];
                float4 pr32[4];
                float  rv[4];
                #pragma unroll
                for (int m = 0; m < 4; m++) {
                    const int k = 4 * p + m;
                    float4 v   = W4[k * WROW4 + lane];
                    float4 v32 = make_float4(0.f, 0.f, 0.f, 0.f);
                    if (lane == 0) v32 = W4[k * WROW4 + 32];
                    #pragma unroll
                    for (int j = 0; j < 3; j++) {
                        if (j < m) {
                            float elem = (j == 0) ? v.x : ((j == 1) ? v.y : v.z);
                            float fj = __shfl_sync(FULL, elem * rv[j], p);
                            v.x = fmaf(-fj, pr[j].x, v.x);
                            v.y = fmaf(-fj, pr[j].y, v.y);
                            v.z = fmaf(-fj, pr[j].z, v.z);
                            v.w = fmaf(-fj, pr[j].w, v.w);
                            if (lane == 0) {
                                v32.x = fmaf(-fj, pr32[j].x, v32.x);
                                v32.y = fmaf(-fj, pr32[j].y, v32.y);
                                v32.z = fmaf(-fj, pr32[j].z, v32.z);
                                v32.w = fmaf(-fj, pr32[j].w, v32.w);
                            }
                        }
                    }
                    float dg = (m == 0) ? v.x : ((m == 1) ? v.y : ((m == 2) ? v.z : v.w));
                    float rm = __shfl_sync(FULL, fast_rcp(dg), p);
                    rv[m] = rm;
                    pr[m] = v;
                    prow4[m * WROW4 + lane] = v;
                    if (lane == 0) {
                        pr32[m] = v32;
                        prow4[m * WROW4 + 32] = v32;
                        rinv_s[m] = rm;
                    }
                }
            }
            __syncthreads();

            if (row > 4 * p + 3) {
                float4 cp  = W4[row * WROW4 + p];
                float4 pp0 = prow4[0 * WROW4 + p];
                float4 pp1 = prow4[1 * WROW4 + p];
                float4 pp2 = prow4[2 * WROW4 + p];
                float r0 = rinv_s[0], r1 = rinv_s[1], r2 = rinv_s[2], r3 = rinv_s[3];

                float f0 = cp.x * r0;
                cp.y = fmaf(-f0, pp0.y, cp.y);
                float f1 = cp.y * r1;
                cp.z = fmaf(-f1, pp1.z, fmaf(-f0, pp0.z, cp.z));
                float f2 = cp.z * r2;
                cp.w = fmaf(-f2, pp2.w, fmaf(-f1, pp1.w, fmaf(-f0, pp0.w, cp.w)));
                float f3 = cp.w * r3;

                const float4* q0r = prow4 + 0 * WROW4;
                const float4* q1r = prow4 + 1 * WROW4;
                const float4* q2r = prow4 + 2 * WROW4;
                const float4* q3r = prow4 + 3 * WROW4;
                float4* wr = W4 + row * WROW4;
                #pragma unroll 2
                for (int g = p + 1 + half; g < WROW4; g += 2) {
                    float4 a  = wr[g];
                    float4 q0 = q0r[g], q1 = q1r[g], q2 = q2r[g], q3 = q3r[g];
                    a.x = fmaf(-f0, q0.x, fmaf(-f1, q1.x, fmaf(-f2, q2.x, fmaf(-f3, q3.x, a.x))));
                    a.y = fmaf(-f0, q0.y, fmaf(-f1, q1.y, fmaf(-f2, q2.y, fmaf(-f3, q3.y, a.y))));
                    a.z = fmaf(-f0, q0.z, fmaf(-f1, q1.z, fmaf(-f2, q2.z, fmaf(-f3, q3.z, a.z))));
                    a.w = fmaf(-f0, q0.w, fmaf(-f1, q1.w, fmaf(-f2, q2.w, fmaf(-f3, q3.w, a.w))));
                    wr[g] = a;
                }
            } else {
                int cidx   = row * 2 + half;
                int stride = 8 * (p + 1);
                for (int idx = cidx; idx < 4 * WROW4; idx += stride)
                    W4[(4 * p + idx / WROW4) * WROW4 + (idx % WROW4)] = prow4[idx];
            }
            __syncthreads();
        }

        for (int k = N_SZ - 1; k >= 0; k--) {
            if (half == 0) {
                float rinv = fast_rcp(Wf[k * WROW + k]);
                float zk0 = Wf[k * WROW + 128] * rinv;
                float zk1 = Wf[k * WROW + 129] * rinv;
                if (row < k) {
                    float a = Wf[row * WROW + k];
                    Wf[row * WROW + 128] = fmaf(-a, zk0, Wf[row * WROW + 128]);
                    Wf[row * WROW + 129] = fmaf(-a, zk1, Wf[row * WROW + 129]);
                } else if (row == k) {
                    z0s[k] = zk0;
                    z1s[k] = zk1;
                }
            }
            __syncthreads();
        }

        if (half == 0) {
            float q0 = z0s[row], q1 = z1s[row];
            #pragma unroll 4
            for (int k = 0; k < N_SZ; k++) {
                float a = Bs[row * BSROW + k] - Bs[k * BSROW + row];
                q0 = fmaf(-a, z0s[k], q0);
                q1 = fmaf(-a, z1s[k], q1);
            }
            g_q0[row] = q0;
            g_q1[row] = q1;
        }
        __syncthreads();
        __threadfence();
        if (tid == 0) *(volatile int*)&g_qdone = 1;
    } else if (blockIdx.x <= 8) {
        // ====== Leaky RNN producer: 1 warp, 32 seqs ======
        if (tid >= 32) return;
        const int j   = (int)blockIdx.x - 1;     // RNN block id
        const int seq = j * 32 + tid;

        const float W00 = 0.1f * wRec[0], W01 = 0.1f * wRec[1];
        const float W10 = 0.1f * wRec[2], W11 = 0.1f * wRec[3];

        const float2* gc = g_c;
        float2* hp = (float2*)g_h;
        float y0 = 0.0f, y1 = 0.0f;

        #define RNN_STEP2(CC, TT)                                               \
            {                                                                   \
                float a0 = fmaf(0.9f, y0, CC.x);                                \
                float a1 = fmaf(0.9f, y1, CC.y);                                \
                float r0 = fmaxf(y0, 0.0f);                                     \
                float r1 = fmaxf(y1, 0.0f);                                     \
                float t0 = fmaf(W00, r0, a0);                                   \
                float t1 = fmaf(W10, r0, a1);                                   \
                y0 = fmaf(W01, r1, t0);                                         \
                y1 = fmaf(W11, r1, t1);                                         \
                hp[(TT) * B_SZ + seq] = make_float2(y0, y1);                    \
            }

        #define LOADG(P, G)                                                     \
            {                                                                   \
                int gg_ = (G) < 255 ? (G) : 255;                                \
                const float2* cp_ = gc + (size_t)gg_ * 8 * B_SZ + seq;          \
                P##0 = __ldg(cp_ + 0 * B_SZ); P##1 = __ldg(cp_ + 1 * B_SZ);     \
                P##2 = __ldg(cp_ + 2 * B_SZ); P##3 = __ldg(cp_ + 3 * B_SZ);     \
                P##4 = __ldg(cp_ + 4 * B_SZ); P##5 = __ldg(cp_ + 5 * B_SZ);     \
                P##6 = __ldg(cp_ + 6 * B_SZ); P##7 = __ldg(cp_ + 7 * B_SZ);     \
            }

        #define RNN_G8(P, TB)                                                   \
            {                                                                   \
                RNN_STEP2(P##0, (TB) + 0); RNN_STEP2(P##1, (TB) + 1);           \
                RNN_STEP2(P##2, (TB) + 2); RNN_STEP2(P##3, (TB) + 3);           \
                RNN_STEP2(P##4, (TB) + 4); RNN_STEP2(P##5, (TB) + 5);           \
                RNN_STEP2(P##6, (TB) + 6); RNN_STEP2(P##7, (TB) + 7);           \
            }

        // publish completed 128-step units (rare: every 4 chunks)
        #define PUBLISH(UV)                                                     \
            {                                                                   \
                __threadfence();                                                \
                if (tid == 0) *(volatile int*)&g_prog[j] = (UV);                \
            }

        float2 A0, A1, A2, A3, A4, A5, A6, A7;
        float2 B0, B1, B2, B3, B4, B5, B6, B7;
        float2 C0, C1, C2, C3, C4, C5, C6, C7;
        float2 D0, D1, D2, D3, D4, D5, D6, D7;

        LOADG(A, 0); LOADG(B, 1); LOADG(C, 2);

        // 63 iterations of 4 groups (1 chunk = 32 steps each)
        #pragma unroll 1
        for (int g = 0; g < 252; g += 4) {
            LOADG(D, g + 3);
            RNN_G8(A, (g + 0) * 8);
            LOADG(A, g + 4);
            RNN_G8(B, (g + 1) * 8);
            LOADG(B, g + 5);
            RNN_G8(C, (g + 2) * 8);
            LOADG(C, g + 6);
            RNN_G8(D, (g + 3) * 8);
            int chunks = (g >> 2) + 1;
            if ((chunks & 3) == 0) PUBLISH(chunks >> 2);   // units of 128 steps
        }
        // tail: groups 252..255 = chunk 64
        LOADG(D, 255);
        RNN_G8(A, 252 * 8);
        RNN_G8(B, 253 * 8);
        RNN_G8(C, 254 * 8);
        RNN_G8(D, 255 * 8);
        PUBLISH(16);

        #undef PUBLISH
        #undef RNN_G8
        #undef LOADG
        #undef RNN_STEP2
    } else {
        // ====== Expand consumers: 1024 warps, 4 per sequence ======
        const int gw = ((int)blockIdx.x - 9) * 8 + wid;
        if (gw >= 1024) return;
        const int b    = gw >> 2;        // sequence
        const int part = gw & 3;         // quarter of the timeline
        const int pj   = b >> 5;         // producer RNN block

        // wait for q (backoff polling)
        if (lane == 0) {
            while (*(volatile int*)&g_qdone == 0) __nanosleep(256);
        }
        __syncwarp();
        __threadfence();

        const float4 q0 = ((const float4*)g_q0)[lane];
        const float4 q1 = ((const float4*)g_q1)[lane];
        const float2* hp = (const float2*)g_h;
        float4* o = (float4*)out;

        // 4 units of 128 timesteps each
        for (int unit = part * 4; unit < part * 4 + 4; unit++) {
            if (lane == 0) {
                while (*(volatile int*)&g_prog[pj] < unit + 1) __nanosleep(256);
            }
            __syncwarp();
            __threadfence();

            const int tb = unit * 128;
            #pragma unroll 4
            for (int t4 = 0; t4 < 32; t4++) {
                int t = tb + t4 * 4;
                float2 h0 = hp[(t + 0) * B_SZ + b];
                float2 h1 = hp[(t + 1) * B_SZ + b];
                float2 h2 = hp[(t + 2) * B_SZ + b];
                float2 h3 = hp[(t + 3) * B_SZ + b];

                size_t base = ((size_t)b * T_SZ + t) * 32 + lane;
                float4 v;
                v.x = fmaf(h0.x, q0.x, h0.y * q1.x);
                v.y = fmaf(h0.x, q0.y, h0.y * q1.y);
                v.z = fmaf(h0.x, q0.z, h0.y * q1.z);
                v.w = fmaf(h0.x, q0.w, h0.y * q1.w);
                __stcs(&o[base], v);
                v.x = fmaf(h1.x, q0.x, h1.y * q1.x);
                v.y = fmaf(h1.x, q0.y, h1.y * q1.y);
                v.z = fmaf(h1.x, q0.z, h1.y * q1.z);
                v.w = fmaf(h1.x, q0.w, h1.y * q1.w);
                __stcs(&o[base + 32], v);
                v.x = fmaf(h2.x, q0.x, h2.y * q1.x);
                v.y = fmaf(h2.x, q0.y, h2.y * q1.y);
                v.z = fmaf(h2.x, q0.z, h2.y * q1.z);
                v.w = fmaf(h2.x, q0.w, h2.y * q1.w);
                __stcs(&o[base + 64], v);
                v.x = fmaf(h3.x, q0.x, h3.y * q1.x);
                v.y = fmaf(h3.x, q0.y, h3.y * q1.y);
                v.z = fmaf(h3.x, q0.z, h3.y * q1.z);
                v.w = fmaf(h3.x, q0.w, h3.y * q1.w);
                __stcs(&o[base + 96], v);
            }
        }
    }
}

// ---------------------------------------------------------------------------
extern "C" void kernel_launch(void* const* d_in, const int* in_sizes, int n_in,
                              void* d_out, int out_size) {
    // u = 1572864, matB = 16384, wIn = 6, wRec = 4
    const float *u = nullptr, *matB = nullptr, *wIn = nullptr, *wRec = nullptr;
    for (int i = 0; i < n_in; i++) {
        switch (in_sizes[i]) {
            case 1572864: u    = (const float*)d_in[i]; break;
            case 16384:   matB = (const float*)d_in[i]; break;
            case 6:       wIn  = (const float*)d_in[i]; break;
            case 4:       wRec = (const float*)d_in[i]; break;
        }
    }

    const int smem = (N_SZ * WROW + N_SZ * BSROW + 4 * WROW + 4)
                     * (int)sizeof(float);   // ~135.8 KB -> 1 block/SM
    cudaFuncSetAttribute(phase1_kernel,
                         cudaFuncAttributeMaxDynamicSharedMemorySize, smem);

    // 0) input projection + flag reset
    proj_kernel<<<512, 256>>>(u, wIn);

    // 1) fused solve + RNN + overlapped expand (148 co-resident blocks)
    phase1_kernel<<<148, 256, smem>>>(matB, wRec, (float*)d_out);
}